// round 3
// baseline (speedup 1.0000x reference)
#include <cuda_runtime.h>
#include <cstdint>

#define N_USER 100000
#define N_ITEM 50000
#define N_NODES (N_USER + N_ITEM)
#define EMB 64
#define NNZ 4000000
#define BATCH 4096
#define NSAMP (3 * BATCH)            // 12288 sample rows
#define N_LAYERS 3
#define FLAG_INIT 0x7fffffff
#define BITS_WORDS ((N_NODES + 31) / 32)   // 4688 words = 18.75 KB
#define LIST_CAP (2 * 1024 * 1024)         // 6x headroom over expected ~313K

// Scratch (static device globals — no allocation in kernel_launch)
__device__ float g_prop[(size_t)NSAMP * EMB];  // 3 MB compact accumulator
__device__ int   g_flag[N_NODES];              // node -> canonical sample row
__device__ unsigned g_bits[BITS_WORDS];        // 18.75 KB active-node bitmask
__device__ int   g_count;                      // compacted edge count
__device__ int   g_ld[LIST_CAP];               // dense row per active edge
__device__ int   g_lc[LIST_CAP];               // col per active edge
__device__ float g_lv[LIST_CAP];               // val per active edge

// ---------------------------------------------------------------------------
// Kernel 1: init. Zero bitmask, counter, flags, compact prop.
// ---------------------------------------------------------------------------
__global__ void k_init() {
    int i = blockIdx.x * blockDim.x + threadIdx.x;
    if (i == 0) g_count = 0;
    if (i < BITS_WORDS) g_bits[i] = 0u;
    if (i < N_NODES) g_flag[i] = FLAG_INIT;
    if (i < NSAMP * (EMB / 4)) {
        reinterpret_cast<float4*>(g_prop)[i] = make_float4(0.f, 0.f, 0.f, 0.f);
    }
}

// ---------------------------------------------------------------------------
// Kernel 2: mark. flag[node] = min sample-row referencing node; set bit.
// ---------------------------------------------------------------------------
__global__ void k_mark(const int* __restrict__ users,
                       const int* __restrict__ pos_items,
                       const int* __restrict__ neg_items) {
    int row = blockIdx.x * blockDim.x + threadIdx.x;
    if (row >= NSAMP) return;
    int slot = row / BATCH;
    int i    = row % BATCH;
    int node;
    if (slot == 0)      node = users[i];
    else if (slot == 1) node = N_USER + pos_items[i];
    else                node = N_USER + neg_items[i];
    atomicMin(&g_flag[node], row);
    atomicOr(&g_bits[node >> 5], 1u << (node & 31));
}

// ---------------------------------------------------------------------------
// Kernel 3: scan + compact. 4 edges/thread via int4 row load; bit test is
// L1-hot (18.75 KB mask). Active edges appended SoA via warp-aggregated
// atomicAdd. Dense-id lookup (600 KB table) only for the ~8% active edges.
// ---------------------------------------------------------------------------
__global__ void k_scan(const int*   __restrict__ rows,
                       const int*   __restrict__ cols,
                       const float* __restrict__ vals) {
    int t = blockIdx.x * blockDim.x + threadIdx.x;
    if (t >= NNZ / 4) return;
    int4 r4 = __ldcs(reinterpret_cast<const int4*>(rows) + t);
    int lane = threadIdx.x & 31;
    const int* rr = &r4.x;
#pragma unroll
    for (int j = 0; j < 4; j++) {
        int r = rr[j];
        bool act = (g_bits[r >> 5] >> (r & 31)) & 1u;
        unsigned m = __ballot_sync(0xffffffffu, act);
        if (m) {
            int leader = __ffs(m) - 1;
            int base = 0;
            if (lane == leader) base = atomicAdd(&g_count, __popc(m));
            base = __shfl_sync(0xffffffffu, base, leader);
            if (act) {
                int pos = base + __popc(m & ((1u << lane) - 1u));
                if (pos < LIST_CAP) {
                    int e = t * 4 + j;
                    g_ld[pos] = g_flag[r];
                    g_lc[pos] = __ldcs(cols + e);
                    g_lv[pos] = __ldcs(vals + e);
                }
            }
        }
    }
}

// ---------------------------------------------------------------------------
// Kernel 4: apply. Each half-warp (16 lanes) processes one compacted edge:
// coalesced 256 B embedding-row gather + 4x red.global.add.v4.f32 into the
// 3 MB L2-hot compact accumulator. Grid-stride over device-side count.
// ---------------------------------------------------------------------------
__global__ void k_apply(const float* __restrict__ user_emb,
                        const float* __restrict__ item_emb) {
    int n = g_count;
    if (n > LIST_CAP) n = LIST_CAP;
    int gthreads = gridDim.x * blockDim.x;
    int stride   = gthreads >> 4;                              // records per wave
    int rec      = (blockIdx.x * blockDim.x + threadIdx.x) >> 4;
    int j4       = threadIdx.x & 15;
    for (; rec < n; rec += stride) {
        int   dd = g_ld[rec];
        int   cc = g_lc[rec];
        float vv = g_lv[rec];
        const float* x = (cc < N_USER)
            ? (user_emb + (size_t)cc * EMB)
            : (item_emb + (size_t)(cc - N_USER) * EMB);
        float4 xv = reinterpret_cast<const float4*>(x)[j4];
        float* dst = g_prop + (size_t)dd * EMB + j4 * 4;
        unsigned long long gp = __cvta_generic_to_global(dst);
        asm volatile(
            "red.global.add.v4.f32 [%0], {%1, %2, %3, %4};"
            :: "l"(gp), "f"(vv * xv.x), "f"(vv * xv.y),
               "f"(vv * xv.z), "f"(vv * xv.w)
            : "memory");
    }
}

// ---------------------------------------------------------------------------
// Kernel 5: epilogue gather. out[row][:] = (ego[node] + 3*prop[dense]) / 4
// ---------------------------------------------------------------------------
__global__ void k_gather(const int*   __restrict__ users,
                         const int*   __restrict__ pos_items,
                         const int*   __restrict__ neg_items,
                         const float* __restrict__ user_emb,
                         const float* __restrict__ item_emb,
                         float*       __restrict__ out) {
    int tid = blockIdx.x * blockDim.x + threadIdx.x;
    if (tid >= NSAMP * 16) return;
    int j4   = tid & 15;
    int row  = tid >> 4;
    int slot = row / BATCH;
    int i    = row % BATCH;
    int node;
    if (slot == 0)      node = users[i];
    else if (slot == 1) node = N_USER + pos_items[i];
    else                node = N_USER + neg_items[i];

    int dense = g_flag[node];

    const float* x = (node < N_USER)
        ? (user_emb + (size_t)node * EMB)
        : (item_emb + (size_t)(node - N_USER) * EMB);
    float4 xe = reinterpret_cast<const float4*>(x)[j4];
    float4 pr = reinterpret_cast<const float4*>(g_prop + (size_t)dense * EMB)[j4];
    const float s = 1.0f / (N_LAYERS + 1);
    float4 o;
    o.x = (xe.x + N_LAYERS * pr.x) * s;
    o.y = (xe.y + N_LAYERS * pr.y) * s;
    o.z = (xe.z + N_LAYERS * pr.z) * s;
    o.w = (xe.w + N_LAYERS * pr.w) * s;
    reinterpret_cast<float4*>(out)[(size_t)row * 16 + j4] = o;
}

// ---------------------------------------------------------------------------
extern "C" void kernel_launch(void* const* d_in, const int* in_sizes, int n_in,
                              void* d_out, int out_size) {
    const int*   adj_rows  = (const int*)  d_in[0];
    const int*   adj_cols  = (const int*)  d_in[1];
    const float* adj_vals  = (const float*)d_in[2];
    const float* user_emb  = (const float*)d_in[3];
    const float* item_emb  = (const float*)d_in[4];
    const int*   users     = (const int*)  d_in[5];
    const int*   pos_items = (const int*)  d_in[6];
    const int*   neg_items = (const int*)  d_in[7];
    float*       out       = (float*)d_out;

    const int initN = NSAMP * (EMB / 4);   // largest init range (196608 > N_NODES)
    k_init<<<(initN + 255) / 256, 256>>>();
    k_mark<<<(NSAMP + 255) / 256, 256>>>(users, pos_items, neg_items);
    k_scan<<<(NNZ / 4 + 255) / 256, 256>>>(adj_rows, adj_cols, adj_vals);
    k_apply<<<2048, 256>>>(user_emb, item_emb);
    k_gather<<<(NSAMP * 16 + 255) / 256, 256>>>(users, pos_items, neg_items,
                                                user_emb, item_emb, out);
}

// round 4
// speedup vs baseline: 2.5285x; 2.5285x over previous
#include <cuda_runtime.h>
#include <cstdint>

#define N_USER 100000
#define N_ITEM 50000
#define N_NODES (N_USER + N_ITEM)
#define EMB 64
#define NNZ 4000000
#define BATCH 4096
#define NSAMP (3 * BATCH)            // 12288 sample rows
#define N_LAYERS 3
#define FLAG_INIT 0x7fffffff
#define BITS_WORDS ((N_NODES + 31) / 32)   // 18.75 KB bitmask
#define BUCKET_CAP 160                      // mean deg 26.7, max ~55 -> safe

// Scratch (static device globals — no allocation in kernel_launch)
__device__ float g_prop[(size_t)NSAMP * EMB];          // 3 MB result rows
__device__ int   g_flag[N_NODES];                       // node -> canonical row
__device__ unsigned g_bits[BITS_WORDS];                 // active-node bitmask
__device__ int   g_cursor[NSAMP];                       // per-row edge count
__device__ int2  g_bucket[(size_t)NSAMP * BUCKET_CAP];  // (col, val-bits), 15.7 MB

// ---------------------------------------------------------------------------
// Kernel 1: init. Zero cursors, bitmask, flags.
// ---------------------------------------------------------------------------
__global__ void k_init() {
    int i = blockIdx.x * blockDim.x + threadIdx.x;
    if (i < NSAMP) g_cursor[i] = 0;
    if (i < BITS_WORDS) g_bits[i] = 0u;
    if (i < N_NODES) g_flag[i] = FLAG_INIT;
}

// ---------------------------------------------------------------------------
// Kernel 2: mark. flag[node] = min sample-row referencing node; set bit.
// ---------------------------------------------------------------------------
__global__ void k_mark(const int* __restrict__ users,
                       const int* __restrict__ pos_items,
                       const int* __restrict__ neg_items) {
    int row = blockIdx.x * blockDim.x + threadIdx.x;
    if (row >= NSAMP) return;
    int slot = row / BATCH;
    int i    = row % BATCH;
    int node;
    if (slot == 0)      node = users[i];
    else if (slot == 1) node = N_USER + pos_items[i];
    else                node = N_USER + neg_items[i];
    atomicMin(&g_flag[node], row);
    atomicOr(&g_bits[node >> 5], 1u << (node & 31));
}

// ---------------------------------------------------------------------------
// Kernel 3: scan + bucket. 4 edges/thread via int4 row load; L1-hot bit test.
// Active edges: spread atomicAdd on per-row cursor (12288 distinct addresses,
// no serialization), write packed (col,val) into the row's bucket.
// ---------------------------------------------------------------------------
__global__ void k_scan(const int*   __restrict__ rows,
                       const int*   __restrict__ cols,
                       const float* __restrict__ vals) {
    int t = blockIdx.x * blockDim.x + threadIdx.x;
    if (t >= NNZ / 4) return;
    int4 r4 = __ldcs(reinterpret_cast<const int4*>(rows) + t);
    const int* rr = &r4.x;
#pragma unroll
    for (int j = 0; j < 4; j++) {
        int r = rr[j];
        if ((g_bits[r >> 5] >> (r & 31)) & 1u) {
            int dense = g_flag[r];
            int slot  = atomicAdd(&g_cursor[dense], 1);
            if (slot < BUCKET_CAP) {
                int e = t * 4 + j;
                int c = __ldcs(cols + e);
                float v = __ldcs(vals + e);
                g_bucket[(size_t)dense * BUCKET_CAP + slot] =
                    make_int2(c, __float_as_int(v));
            }
        }
    }
}

// ---------------------------------------------------------------------------
// Kernel 4: accumulate. One warp per dense row; lane owns float2 of the
// 64-dim accumulator. Bucket entries loaded coalesced once, broadcast via
// shfl; per edge one coalesced 256B embedding-row gather; register accum;
// single 256B store. No global atomics.
// ---------------------------------------------------------------------------
__global__ void k_accum(const float* __restrict__ user_emb,
                        const float* __restrict__ item_emb) {
    int warp = (blockIdx.x * blockDim.x + threadIdx.x) >> 5;
    if (warp >= NSAMP) return;
    int lane = threadIdx.x & 31;

    int cnt = g_cursor[warp];
    if (cnt > BUCKET_CAP) cnt = BUCKET_CAP;

    float2 acc = make_float2(0.f, 0.f);
    const int2* bucket = g_bucket + (size_t)warp * BUCKET_CAP;

    for (int base = 0; base < cnt; base += 32) {
        int m = cnt - base;
        if (m > 32) m = 32;
        int2 ent = make_int2(0, 0);
        if (lane < m) ent = bucket[base + lane];
        int k = 0;
        // unrolled by 2 for load pipelining
        for (; k + 1 < m; k += 2) {
            int   c0 = __shfl_sync(0xffffffffu, ent.x, k);
            float v0 = __int_as_float(__shfl_sync(0xffffffffu, ent.y, k));
            int   c1 = __shfl_sync(0xffffffffu, ent.x, k + 1);
            float v1 = __int_as_float(__shfl_sync(0xffffffffu, ent.y, k + 1));
            const float2* x0 = reinterpret_cast<const float2*>(
                (c0 < N_USER) ? user_emb + (size_t)c0 * EMB
                              : item_emb + (size_t)(c0 - N_USER) * EMB);
            const float2* x1 = reinterpret_cast<const float2*>(
                (c1 < N_USER) ? user_emb + (size_t)c1 * EMB
                              : item_emb + (size_t)(c1 - N_USER) * EMB);
            float2 a = x0[lane];
            float2 b = x1[lane];
            acc.x += v0 * a.x; acc.y += v0 * a.y;
            acc.x += v1 * b.x; acc.y += v1 * b.y;
        }
        if (k < m) {
            int   c0 = __shfl_sync(0xffffffffu, ent.x, k);
            float v0 = __int_as_float(__shfl_sync(0xffffffffu, ent.y, k));
            const float2* x0 = reinterpret_cast<const float2*>(
                (c0 < N_USER) ? user_emb + (size_t)c0 * EMB
                              : item_emb + (size_t)(c0 - N_USER) * EMB);
            float2 a = x0[lane];
            acc.x += v0 * a.x; acc.y += v0 * a.y;
        }
    }
    reinterpret_cast<float2*>(g_prop + (size_t)warp * EMB)[lane] = acc;
}

// ---------------------------------------------------------------------------
// Kernel 5: epilogue gather. out[row][:] = (ego[node] + 3*prop[dense]) / 4
// ---------------------------------------------------------------------------
__global__ void k_gather(const int*   __restrict__ users,
                         const int*   __restrict__ pos_items,
                         const int*   __restrict__ neg_items,
                         const float* __restrict__ user_emb,
                         const float* __restrict__ item_emb,
                         float*       __restrict__ out) {
    int tid = blockIdx.x * blockDim.x + threadIdx.x;
    if (tid >= NSAMP * 16) return;
    int j4   = tid & 15;
    int row  = tid >> 4;
    int slot = row / BATCH;
    int i    = row % BATCH;
    int node;
    if (slot == 0)      node = users[i];
    else if (slot == 1) node = N_USER + pos_items[i];
    else                node = N_USER + neg_items[i];

    int dense = g_flag[node];

    const float* x = (node < N_USER)
        ? (user_emb + (size_t)node * EMB)
        : (item_emb + (size_t)(node - N_USER) * EMB);
    float4 xe = reinterpret_cast<const float4*>(x)[j4];
    float4 pr = reinterpret_cast<const float4*>(g_prop + (size_t)dense * EMB)[j4];
    const float s = 1.0f / (N_LAYERS + 1);
    float4 o;
    o.x = (xe.x + N_LAYERS * pr.x) * s;
    o.y = (xe.y + N_LAYERS * pr.y) * s;
    o.z = (xe.z + N_LAYERS * pr.z) * s;
    o.w = (xe.w + N_LAYERS * pr.w) * s;
    reinterpret_cast<float4*>(out)[(size_t)row * 16 + j4] = o;
}

// ---------------------------------------------------------------------------
extern "C" void kernel_launch(void* const* d_in, const int* in_sizes, int n_in,
                              void* d_out, int out_size) {
    const int*   adj_rows  = (const int*)  d_in[0];
    const int*   adj_cols  = (const int*)  d_in[1];
    const float* adj_vals  = (const float*)d_in[2];
    const float* user_emb  = (const float*)d_in[3];
    const float* item_emb  = (const float*)d_in[4];
    const int*   users     = (const int*)  d_in[5];
    const int*   pos_items = (const int*)  d_in[6];
    const int*   neg_items = (const int*)  d_in[7];
    float*       out       = (float*)d_out;

    k_init<<<(N_NODES + 255) / 256, 256>>>();
    k_mark<<<(NSAMP + 255) / 256, 256>>>(users, pos_items, neg_items);
    k_scan<<<(NNZ / 4 + 255) / 256, 256>>>(adj_rows, adj_cols, adj_vals);
    k_accum<<<(NSAMP * 32 + 255) / 256, 256>>>(user_emb, item_emb);
    k_gather<<<(NSAMP * 16 + 255) / 256, 256>>>(users, pos_items, neg_items,
                                                user_emb, item_emb, out);
}